// round 4
// baseline (speedup 1.0000x reference)
#include <cuda_runtime.h>

#define BB 4096
#define FF 256
#define TT 128
#define DD 6
#define UU 16
#define NBIN 64

#define ROWS 32
#define LANES 8
#define THREADS 256
#define TSPLIT 8
#define TPB (TT / TSPLIT)   /* 16 trees per block */
#define XSTRIDE 260         /* 256 + 4 pad: conflict-free LDS.128 across rows */

typedef unsigned long long u64t;

// ---- packed f32x2 helpers (sm_103a FFMA2 path, PTX-only per SASS_QUICKREF) ----
__device__ __forceinline__ u64t ffma2(u64t a, u64t b, u64t c) {
    u64t d;
    asm("fma.rn.f32x2 %0, %1, %2, %3;" : "=l"(d) : "l"(a), "l"(b), "l"(c));
    return d;
}
__device__ __forceinline__ u64t fmul2(u64t a, u64t b) {
    u64t d;
    asm("mul.rn.f32x2 %0, %1, %2;" : "=l"(d) : "l"(a), "l"(b));
    return d;
}
__device__ __forceinline__ u64t pk2(float lo, float hi) {
    u64t p;
    asm("mov.b64 %0, {%1, %2};" : "=l"(p) : "f"(lo), "f"(hi));
    return p;
}
__device__ __forceinline__ float2 unpk2(u64t p) {
    float2 v;
    asm("mov.b64 {%0, %1}, %2;" : "=f"(v.x), "=f"(v.y) : "l"(p));
    return v;
}

// Scratch (device globals: no runtime allocation allowed)
__device__ __align__(16) float g_selW[TT * DD * FF];   // [t][d][f], sparsemax-ed selectors
__device__ __align__(16) float g_a[TT * DD];           // 0.5*exp(-lt)
__device__ __align__(16) float g_b[TT * DD];           // 0.5 - th*a

// ---------------------------------------------------------------------------
// Prep: sparsemax over D=6 per (f,t); also the per-(t,d) affine for sparsemoid
// ---------------------------------------------------------------------------
__global__ void prep_kernel(const float* __restrict__ fsl,
                            const float* __restrict__ th,
                            const float* __restrict__ lt)
{
    int n = blockIdx.x * blockDim.x + threadIdx.x;

    if (n < TT * DD) {
        float a = 0.5f * expf(-lt[n]);
        g_a[n] = a;
        g_b[n] = 0.5f - th[n] * a;
    }
    if (n >= FF * TT) return;

    int f = n / TT;
    int t = n - f * TT;

    const float* zp = fsl + (size_t)f * (TT * DD) + t * DD;
    float z[DD], zs[DD];
#pragma unroll
    for (int d = 0; d < DD; ++d) { z[d] = zp[d]; zs[d] = z[d]; }

    // descending bubble sorting network (15 comparators, D=6)
#pragma unroll
    for (int p = 0; p < DD - 1; ++p) {
#pragma unroll
        for (int i = 0; i < DD - 1 - p; ++i) {
            float mx = fmaxf(zs[i], zs[i + 1]);
            float mn = fminf(zs[i], zs[i + 1]);
            zs[i] = mx; zs[i + 1] = mn;
        }
    }

    // sparsemax threshold
    float cs = 0.f, css = 0.f;
    int kz = 0;
#pragma unroll
    for (int k = 1; k <= DD; ++k) {
        cs += zs[k - 1];
        if (1.0f + (float)k * zs[k - 1] > cs) { kz = k; css = cs; }
    }
    float tau = (css - 1.0f) / (float)kz;

#pragma unroll
    for (int d = 0; d < DD; ++d)
        g_selW[(size_t)(t * DD + d) * FF + f] = fmaxf(z[d] - tau, 0.0f);
}

// ---------------------------------------------------------------------------
// Fused main kernel: fv GEMM -> sparsemoid -> product tree -> response GEMM
// block = 32 batch rows x 16 trees; thread = (row, tree-lane of 8)
// ---------------------------------------------------------------------------
__global__ void __launch_bounds__(THREADS, 1)
main_kernel(const float* __restrict__ x,
            const float* __restrict__ resp,
            float* __restrict__ out)
{
    extern __shared__ float sm[];
    float* xs  = sm;                                // ROWS*XSTRIDE   (8320)
    float* sel = xs + ROWS * XSTRIDE;               // LANES*DD*FF    (12288)
    float* rs  = sel + LANES * DD * FF;             // LANES*UU*NBIN  (8192)
    float* red = rs + LANES * UU * NBIN;            // ROWS*UU        (512)
    float* sa  = red + ROWS * UU;                   // TPB*DD         (96)
    float* sb  = sa + TPB * DD;                     // TPB*DD         (96)

    const int tid  = threadIdx.x;
    const int row  = tid & (ROWS - 1);
    const int lane = tid >> 5;
    const int b0   = blockIdx.x * ROWS;
    const int t0   = blockIdx.y * TPB;

    // load x tile (coalesced gmem -> padded smem)
    for (int i = tid; i < ROWS * (FF / 4); i += THREADS) {
        int r = i >> 6, c4 = i & 63;
        float4 v = reinterpret_cast<const float4*>(x + (size_t)(b0 + r) * FF)[c4];
        *reinterpret_cast<float4*>(xs + r * XSTRIDE + 4 * c4) = v;
    }
    for (int i = tid; i < ROWS * UU; i += THREADS) red[i] = 0.f;
    for (int i = tid; i < TPB * DD; i += THREADS) {
        sa[i] = g_a[t0 * DD + i];
        sb[i] = g_b[t0 * DD + i];
    }

    // packed accumulators: acc2a/acc2b hold (even,odd)-bin partial sums per u
    u64t acc2a[UU], acc2b[UU];
#pragma unroll
    for (int u = 0; u < UU; ++u) { acc2a[u] = 0ULL; acc2b[u] = 0ULL; }

    for (int tg = 0; tg < TPB; tg += LANES) {
        __syncthreads();
        // stage selectors + responses for 8 trees (contiguous slabs)
        {
            const float4* ssrc = reinterpret_cast<const float4*>(
                g_selW + (size_t)(t0 + tg) * DD * FF);
            float4* sdst = reinterpret_cast<float4*>(sel);
            for (int i = tid; i < LANES * DD * FF / 4; i += THREADS) sdst[i] = ssrc[i];

            const float4* rsrc = reinterpret_cast<const float4*>(
                resp + (size_t)(t0 + tg) * UU * NBIN);
            float4* rdst = reinterpret_cast<float4*>(rs);
            for (int i = tid; i < LANES * UU * NBIN / 4; i += THREADS) rdst[i] = rsrc[i];
        }
        __syncthreads();

        const float*      selT  = sel + lane * DD * FF;
        const float*      respT = rs + lane * UU * NBIN;
        const ulonglong2* xr2   = reinterpret_cast<const ulonglong2*>(xs + row * XSTRIDE);

        // hoist per-tree affine into registers
        const int tl = (tg + lane) * DD;
        float ra[DD], rb[DD];
#pragma unroll
        for (int d = 0; d < DD; ++d) { ra[d] = sa[tl + d]; rb[d] = sb[tl + d]; }

        // fv[d] = x_row . sel[d]  -- 12 independent packed FMA chains
        u64t pa[DD], pb[DD];
#pragma unroll
        for (int d = 0; d < DD; ++d) { pa[d] = 0ULL; pb[d] = 0ULL; }
#pragma unroll 4
        for (int k4 = 0; k4 < FF / 4; ++k4) {
            ulonglong2 xv = xr2[k4];
#pragma unroll
            for (int d = 0; d < DD; ++d) {
                ulonglong2 sv = reinterpret_cast<const ulonglong2*>(selT + d * FF)[k4];
                pa[d] = ffma2(xv.x, sv.x, pa[d]);
                pb[d] = ffma2(xv.y, sv.y, pb[d]);
            }
        }

        // sparsemoid: s = clamp(fv*a + b, 0, 1)
        float s[DD];
#pragma unroll
        for (int d = 0; d < DD; ++d) {
            float2 va = unpk2(pa[d]);
            float2 vb = unpk2(pb[d]);
            float fv = (va.x + va.y) + (vb.x + vb.y);
            s[d] = __saturatef(fv * ra[d] + rb[d]);
        }

        // product tree over depths 1..5 -> v[32]; then fold depth 0 into pairs:
        // w[2j] = v[j]*s0, w[2j+1] = v[j]*(1-s0)   (bit0 of leaf index uses s[0])
        float v[NBIN / 2];
        v[0] = s[1];
        v[1] = 1.0f - s[1];
#pragma unroll
        for (int d = 2; d < DD; ++d) {
#pragma unroll
            for (int c = 0; c < (1 << (d - 1)); ++c) {
                float lo = v[c];
                v[c] = lo * s[d];
                v[c + (1 << (d - 1))] = lo * (1.0f - s[d]);
            }
        }
        const u64t s0pair = pk2(s[0], 1.0f - s[0]);
        u64t w2[NBIN / 2];
#pragma unroll
        for (int j = 0; j < NBIN / 2; ++j)
            w2[j] = fmul2(pk2(v[j], v[j]), s0pair);

        // out_u += w . resp[t][u][:]  -- packed, two chains per u
#pragma unroll
        for (int u = 0; u < UU; ++u) {
            const ulonglong2* rr = reinterpret_cast<const ulonglong2*>(respT + u * NBIN);
            u64t ca = acc2a[u], cb = acc2b[u];
#pragma unroll
            for (int q = 0; q < NBIN / 4; ++q) {
                ulonglong2 rv = rr[q];
                ca = ffma2(w2[2 * q + 0], rv.x, ca);
                cb = ffma2(w2[2 * q + 1], rv.y, cb);
            }
            acc2a[u] = ca; acc2b[u] = cb;
        }
    }

    // reduce the 8 tree-lanes per row via shared atomics
#pragma unroll
    for (int u = 0; u < UU; ++u) {
        float2 a2 = unpk2(acc2a[u]);
        float2 b2 = unpk2(acc2b[u]);
        atomicAdd(&red[row * UU + u], (a2.x + a2.y) + (b2.x + b2.y));
    }
    __syncthreads();

    // cross-block (tree-split) accumulation into zeroed output
    for (int i = tid; i < ROWS * UU; i += THREADS) {
        atomicAdd(&out[(size_t)(b0 + i / UU) * UU + (i % UU)], red[i]);
    }
}

// ---------------------------------------------------------------------------
extern "C" void kernel_launch(void* const* d_in, const int* in_sizes, int n_in,
                              void* d_out, int out_size)
{
    const float* x    = (const float*)d_in[0];
    const float* fsl  = (const float*)d_in[1];
    const float* th   = (const float*)d_in[2];
    const float* lt   = (const float*)d_in[3];
    const float* resp = (const float*)d_in[4];
    float* out = (float*)d_out;

    cudaMemsetAsync(out, 0, (size_t)out_size * sizeof(float));

    prep_kernel<<<(FF * TT + 255) / 256, 256>>>(fsl, th, lt);

    const int smem = (ROWS * XSTRIDE + LANES * DD * FF + LANES * UU * NBIN +
                      ROWS * UU + 2 * TPB * DD) * (int)sizeof(float);
    cudaFuncSetAttribute(main_kernel, cudaFuncAttributeMaxDynamicSharedMemorySize, smem);
    main_kernel<<<dim3(BB / ROWS, TSPLIT), THREADS, smem>>>(x, resp, out);
}